// round 1
// baseline (speedup 1.0000x reference)
#include <cuda_runtime.h>

#define THREADS 256
#define E_TILE  64
#define KDIM    84
#define APAD    88          // sA row stride (floats), 16B-aligned, covers 84 + pad
#define NOUT    128
#define MAX_GRID 296        // 148 SMs * 2 CTAs

__device__ int g_is64;

// Detect int64 vs int32 index buffer: for int64 (values in [0,100000)) every
// odd 32-bit word is exactly 0. Probability of that for 4096 random int32
// indices is ~(1e-5)^4096 ~ 0.
__global__ void detect_idx_kernel(const unsigned* __restrict__ bi) {
    int ok = 1;
    for (int i = threadIdx.x; i < 4096; i += blockDim.x)
        if (bi[2 * i + 1] != 0u) ok = 0;
    ok = __syncthreads_and(ok);
    if (threadIdx.x == 0) g_is64 = ok;
}

__device__ __forceinline__ unsigned smem_u32(const void* p) {
    return (unsigned)__cvta_generic_to_shared(p);
}

#define FMA2(acc, a, w) asm("fma.rn.f32x2 %0, %1, %2, %0;" : "+l"(acc) : "l"(a), "l"(w))

__device__ __forceinline__ unsigned long long bcast2(float v) {
    unsigned long long r;
    asm("mov.b64 %0, {%1, %1};" : "=l"(r) : "f"(v));
    return r;
}

__device__ __forceinline__ float2 ull2f2(unsigned long long v) {
    float2 r;
    asm("mov.b64 {%0, %1}, %2;" : "=f"(r.x), "=f"(r.y) : "l"(v));
    return r;
}

// One K step: 4 edges x 8 cols of packed-f32x2 FMA against an smem W row.
__device__ __forceinline__ void kstep(const float* __restrict__ sWk, int cg,
                                      float av0, float av1, float av2, float av3,
                                      unsigned long long acc[4][4]) {
    const ulonglong2* wp = reinterpret_cast<const ulonglong2*>(sWk + cg * 8);
    ulonglong2 wA = wp[0];   // cols +0..+3 as two f32x2
    ulonglong2 wB = wp[1];   // cols +4..+7
    unsigned long long a0 = bcast2(av0), a1 = bcast2(av1);
    unsigned long long a2 = bcast2(av2), a3 = bcast2(av3);
    FMA2(acc[0][0], a0, wA.x); FMA2(acc[0][1], a0, wA.y); FMA2(acc[0][2], a0, wB.x); FMA2(acc[0][3], a0, wB.y);
    FMA2(acc[1][0], a1, wA.x); FMA2(acc[1][1], a1, wA.y); FMA2(acc[1][2], a1, wB.x); FMA2(acc[1][3], a1, wB.y);
    FMA2(acc[2][0], a2, wA.x); FMA2(acc[2][1], a2, wA.y); FMA2(acc[2][2], a2, wB.x); FMA2(acc[2][3], a2, wB.y);
    FMA2(acc[3][0], a3, wA.x); FMA2(acc[3][1], a3, wA.y); FMA2(acc[3][2], a3, wB.x); FMA2(acc[3][3], a3, wB.y);
}

// Async-copy one tile's bond_feat [64 x 64 f32] into sA rows (cols 0..63).
__device__ __forceinline__ void issue_tile_copy(const float* __restrict__ bond_feat,
                                                long long E, long long tile_base,
                                                unsigned sbase, int tid) {
#pragma unroll
    for (int i = 0; i < 4; i++) {                 // 1024 x 16B chunks / 256 thr
        int c = tid + i * THREADS;
        int e = c >> 4;                           // edge within tile
        int q = c & 15;                           // 16B chunk within row
        long long eg = tile_base + e;
        if (eg >= E) eg = E - 1;                  // clamp (harmless dup)
        const float* src = bond_feat + eg * 64 + q * 4;
        unsigned dst = sbase + (unsigned)((e * APAD + q * 4) * 4);
        asm volatile("cp.async.cg.shared.global [%0], [%1], 16;" :: "r"(dst), "l"(src));
    }
    asm volatile("cp.async.commit_group;" ::: "memory");
}

// Gaussian smearing for one tile: 4 threads per edge, 5 gaussians each -> sA cols 64..83.
__device__ __forceinline__ void gauss_tile(const void* __restrict__ bond_index, int is64,
                                           const float* __restrict__ pos,
                                           long long E, long long tile_base,
                                           float* __restrict__ sA, int tid) {
    int e = tid >> 2;
    int q = tid & 3;
    long long eg = tile_base + e;
    if (eg >= E) eg = E - 1;
    long long i0, i1;
    if (is64) {
        const long long* bi = (const long long*)bond_index;
        i0 = bi[eg];
        i1 = bi[E + eg];
    } else {
        const int* bi = (const int*)bond_index;
        i0 = (long long)bi[eg];
        i1 = (long long)bi[E + eg];
    }
    float dx = pos[i0 * 3 + 0] - pos[i1 * 3 + 0];
    float dy = pos[i0 * 3 + 1] - pos[i1 * 3 + 1];
    float dz = pos[i0 * 3 + 2] - pos[i1 * 3 + 2];
    float dist = sqrtf(dx * dx + dy * dy + dz * dz);
    const float delta = 10.0f / 19.0f;            // linspace(0,10,20) spacing
    const float coeff = -0.5f / (delta * delta);
    float* dstp = sA + e * APAD + 64 + q * 5;
#pragma unroll
    for (int j = 0; j < 5; j++) {
        float d = dist - (float)(q * 5 + j) * delta;
        dstp[j] = expf(coeff * d * d);
    }
}

__global__ void __launch_bounds__(THREADS, 2)
bond_embed_kernel(const float* __restrict__ bond_feat,
                  const void* __restrict__ bond_index,
                  const float* __restrict__ pos,
                  const float* __restrict__ W,
                  const float* __restrict__ bias,
                  float* __restrict__ out,
                  long long E, int nTiles) {
    extern __shared__ float smem[];
    float* sW  = smem;                          // 84*128 f32
    float* sA0 = sW + KDIM * NOUT;              // 64*88
    float* sA1 = sA0 + E_TILE * APAD;           // 64*88

    const int tid = threadIdx.x;
    const int eg4 = (tid >> 4) * 4;             // first of this thread's 4 edges
    const int cg  = tid & 15;                   // col group (8 cols)
    const int is64 = g_is64;

    // Cooperative W load (once per CTA; persistent tile loop amortizes it)
    {
        const float4* Wv = reinterpret_cast<const float4*>(W);
        float4* sWv = reinterpret_cast<float4*>(sW);
#pragma unroll
        for (int i = 0; i < (KDIM * NOUT / 4 + THREADS - 1) / THREADS; i++) {
            int idx = tid + i * THREADS;
            if (idx < KDIM * NOUT / 4) sWv[idx] = Wv[idx];
        }
    }
    float4 b0 = reinterpret_cast<const float4*>(bias)[cg * 2];
    float4 b1 = reinterpret_cast<const float4*>(bias)[cg * 2 + 1];

    int tile = blockIdx.x;
    if (tile >= nTiles) return;                 // uniform per-block

    // Prologue: stage tile 0 into buffer 0
    issue_tile_copy(bond_feat, E, (long long)tile * E_TILE, smem_u32(sA0), tid);
    gauss_tile(bond_index, is64, pos, E, (long long)tile * E_TILE, sA0, tid);
    asm volatile("cp.async.wait_group 0;" ::: "memory");
    __syncthreads();

    int cur = 0;
    while (tile < nTiles) {
        float* sA  = cur ? sA1 : sA0;
        float* sAn = cur ? sA0 : sA1;
        int nxt = tile + (int)gridDim.x;

        if (nxt < nTiles)
            issue_tile_copy(bond_feat, E, (long long)nxt * E_TILE, smem_u32(sAn), tid);

        unsigned long long acc[4][4];
#pragma unroll
        for (int j = 0; j < 4; j++)
#pragma unroll
            for (int p = 0; p < 4; p++) acc[j][p] = 0ull;

        const float* a0p = sA + (eg4 + 0) * APAD;
        const float* a1p = sA + (eg4 + 1) * APAD;
        const float* a2p = sA + (eg4 + 2) * APAD;
        const float* a3p = sA + (eg4 + 3) * APAD;

#pragma unroll 3
        for (int kk = 0; kk < KDIM; kk += 4) {
            float4 va0 = *reinterpret_cast<const float4*>(a0p + kk);
            float4 va1 = *reinterpret_cast<const float4*>(a1p + kk);
            float4 va2 = *reinterpret_cast<const float4*>(a2p + kk);
            float4 va3 = *reinterpret_cast<const float4*>(a3p + kk);
            kstep(sW + (kk + 0) * NOUT, cg, va0.x, va1.x, va2.x, va3.x, acc);
            kstep(sW + (kk + 1) * NOUT, cg, va0.y, va1.y, va2.y, va3.y, acc);
            kstep(sW + (kk + 2) * NOUT, cg, va0.z, va1.z, va2.z, va3.z, acc);
            kstep(sW + (kk + 3) * NOUT, cg, va0.w, va1.w, va2.w, va3.w, acc);
        }

        // Epilogue: bias + coalesced STG.128 x2 per edge
        long long base = (long long)tile * E_TILE + eg4;
#pragma unroll
        for (int j = 0; j < 4; j++) {
            long long e = base + j;
            if (e < E) {
                float2 p0 = ull2f2(acc[j][0]);
                float2 p1 = ull2f2(acc[j][1]);
                float2 p2 = ull2f2(acc[j][2]);
                float2 p3 = ull2f2(acc[j][3]);
                float4 r0 = make_float4(p0.x + b0.x, p0.y + b0.y, p1.x + b0.z, p1.y + b0.w);
                float4 r1 = make_float4(p2.x + b1.x, p2.y + b1.y, p3.x + b1.z, p3.y + b1.w);
                float* op = out + e * NOUT + cg * 8;
                reinterpret_cast<float4*>(op)[0] = r0;
                reinterpret_cast<float4*>(op)[1] = r1;
            }
        }

        if (nxt < nTiles)
            gauss_tile(bond_index, is64, pos, E, (long long)nxt * E_TILE, sAn, tid);
        asm volatile("cp.async.wait_group 0;" ::: "memory");
        __syncthreads();
        cur ^= 1;
        tile = nxt;
    }
}

extern "C" void kernel_launch(void* const* d_in, const int* in_sizes, int n_in,
                              void* d_out, int out_size) {
    const float* bond_feat  = (const float*)d_in[0];
    const void*  bond_index = (const void*)d_in[1];
    const float* pos        = (const float*)d_in[2];
    const float* W          = (const float*)d_in[3];
    const float* bias       = (const float*)d_in[4];
    float* out = (float*)d_out;

    long long E = (long long)(in_sizes[0] / 64);          // bond_feat is [E, 64]
    int nTiles = (int)((E + E_TILE - 1) / E_TILE);
    int grid = nTiles < MAX_GRID ? nTiles : MAX_GRID;

    size_t smem = (size_t)(KDIM * NOUT + 2 * E_TILE * APAD) * sizeof(float); // 88064 B
    cudaFuncSetAttribute(bond_embed_kernel,
                         cudaFuncAttributeMaxDynamicSharedMemorySize, (int)smem);

    detect_idx_kernel<<<1, 256>>>((const unsigned*)bond_index);
    bond_embed_kernel<<<grid, THREADS, smem>>>(bond_feat, bond_index, pos, W, bias,
                                               out, E, nTiles);
}

// round 3
// speedup vs baseline: 2.5368x; 2.5368x over previous
#include <cuda_runtime.h>
#include <cuda_fp16.h>
#include <cstdint>

#define THREADS 256
#define NOUT 128
#define KLOG 84
#define SA_STRIDE 208              // bytes per A row (104 halves: 96 k + pad)
#define SA_SPLIT  26624            // 128 rows * 208 B (one of hi/lo)
#define SA_BUF    (2 * SA_SPLIT)   // hi + lo
#define SMEM_TOTAL (2 * SA_BUF)    // double buffered: 106496 B

__device__ int g_is64;

// int64 vs int32 index detection (values < 1e5 => odd words all zero for i64)
__global__ void detect_idx_kernel(const unsigned* __restrict__ bi) {
    int ok = 1;
    for (int i = threadIdx.x; i < 4096; i += blockDim.x)
        if (bi[2 * i + 1] != 0u) ok = 0;
    ok = __syncthreads_and(ok);
    if (threadIdx.x == 0) g_is64 = ok;
}

__device__ __forceinline__ uint32_t smem_u32(const void* p) {
    return (uint32_t)__cvta_generic_to_shared(p);
}

__device__ __forceinline__ uint32_t pack_h2(float a, float b) {
    __half2 h = __floats2half2_rn(a, b);
    return *reinterpret_cast<uint32_t*>(&h);
}

// split 8 floats into fp16 hi (rn) and fp16 lo (residual)
__device__ __forceinline__ void split8h(const float* x, uint4& hi, uint4& lo) {
    uint32_t hh[4], ll[4];
#pragma unroll
    for (int p = 0; p < 4; p++) {
        float a = x[2 * p], b = x[2 * p + 1];
        __half2 h2 = __floats2half2_rn(a, b);
        float ra = a - __half2float(__low2half(h2));
        float rb = b - __half2float(__high2half(h2));
        __half2 l2 = __floats2half2_rn(ra, rb);
        hh[p] = *reinterpret_cast<uint32_t*>(&h2);
        ll[p] = *reinterpret_cast<uint32_t*>(&l2);
    }
    hi = make_uint4(hh[0], hh[1], hh[2], hh[3]);
    lo = make_uint4(ll[0], ll[1], ll[2], ll[3]);
}

#define LDSM_X4(r0, r1, r2, r3, addr)                                          \
    asm volatile("ldmatrix.sync.aligned.m8n8.x4.shared.b16 {%0,%1,%2,%3}, [%4];" \
                 : "=r"(r0), "=r"(r1), "=r"(r2), "=r"(r3) : "r"(addr))

#define MMA16816(c, a, b)                                                      \
    asm volatile("mma.sync.aligned.m16n8k16.row.col.f32.f16.f16.f32 "          \
                 "{%0,%1,%2,%3}, {%4,%5,%6,%7}, {%8,%9}, {%0,%1,%2,%3};"       \
                 : "+f"((c)[0]), "+f"((c)[1]), "+f"((c)[2]), "+f"((c)[3])      \
                 : "r"((a)[0]), "r"((a)[1]), "r"((a)[2]), "r"((a)[3]),         \
                   "r"((b)[0]), "r"((b)[1]))

__device__ __forceinline__ void prefetch(const float* __restrict__ bond_feat,
                                         const void* __restrict__ bidx, int is64,
                                         const float* __restrict__ pos,
                                         long long E, long long tile, int tid,
                                         float4 f[8], float& dist) {
    long long tbase = tile << 7;
    int e = tid >> 1, h = tid & 1;
    long long eg = tbase + e;
    if (eg >= E) eg = E - 1;
    const float4* src = reinterpret_cast<const float4*>(bond_feat) + eg * 16 + h * 8;
#pragma unroll
    for (int q = 0; q < 8; q++) f[q] = src[q];
    if (tid < 128) {
        long long eg2 = tbase + tid;
        if (eg2 >= E) eg2 = E - 1;
        long long i0, i1;
        if (is64) {
            const long long* b = (const long long*)bidx;
            i0 = b[eg2]; i1 = b[E + eg2];
        } else {
            const int* b = (const int*)bidx;
            i0 = (long long)b[eg2]; i1 = (long long)b[E + eg2];
        }
        float dx = pos[i0 * 3 + 0] - pos[i1 * 3 + 0];
        float dy = pos[i0 * 3 + 1] - pos[i1 * 3 + 1];
        float dz = pos[i0 * 3 + 2] - pos[i1 * 3 + 2];
        dist = sqrtf(dx * dx + dy * dy + dz * dz);
    }
}

__device__ __forceinline__ void fill_tile(char* sA, const float4 f[8], float dist, int tid) {
    char* aH = sA;
    char* aL = sA + SA_SPLIT;
    int e = tid >> 1, h = tid & 1;
    int rb = e * SA_STRIDE + h * 64;
#pragma unroll
    for (int q = 0; q < 4; q++) {
        float xs[8] = { f[2*q].x, f[2*q].y, f[2*q].z, f[2*q].w,
                        f[2*q+1].x, f[2*q+1].y, f[2*q+1].z, f[2*q+1].w };
        uint4 hi, lo;
        split8h(xs, hi, lo);
        *reinterpret_cast<uint4*>(aH + rb + q * 16) = hi;
        *reinterpret_cast<uint4*>(aL + rb + q * 16) = lo;
    }
    if (tid < 128) {
        float gg[20];
        const float delta = 10.0f / 19.0f;
        const float coeff = -0.5f / (delta * delta);
#pragma unroll
        for (int j = 0; j < 20; j++) {
            float d = dist - (float)j * delta;
            gg[j] = expf(coeff * d * d);
        }
        int row = tid * SA_STRIDE;
        uint4 h0, l0, h1, l1;
        split8h(gg, h0, l0);
        split8h(gg + 8, h1, l1);
        *reinterpret_cast<uint4*>(aH + row + 128) = h0;
        *reinterpret_cast<uint4*>(aL + row + 128) = l0;
        *reinterpret_cast<uint4*>(aH + row + 144) = h1;
        *reinterpret_cast<uint4*>(aL + row + 144) = l1;
        uint32_t th0 = pack_h2(gg[16], gg[17]);
        uint32_t th1 = pack_h2(gg[18], gg[19]);
        __half2 v0 = *reinterpret_cast<__half2*>(&th0);
        __half2 v1 = *reinterpret_cast<__half2*>(&th1);
        uint32_t tl0 = pack_h2(gg[16] - __half2float(__low2half(v0)),
                               gg[17] - __half2float(__high2half(v0)));
        uint32_t tl1 = pack_h2(gg[18] - __half2float(__low2half(v1)),
                               gg[19] - __half2float(__high2half(v1)));
        *reinterpret_cast<uint2*>(aH + row + 160) = make_uint2(th0, th1);
        *reinterpret_cast<uint2*>(aL + row + 160) = make_uint2(tl0, tl1);
    }
}

__global__ void __launch_bounds__(THREADS, 1)
bond_embed_mma(const float* __restrict__ bond_feat,
               const void* __restrict__ bond_index,
               const float* __restrict__ pos,
               const float* __restrict__ W,
               const float* __restrict__ bias,
               float* __restrict__ out,
               long long E) {
    extern __shared__ char smem[];
    const uint32_t sb = smem_u32(smem);
    const int tid = threadIdx.x;
    const int warp = tid >> 5, lane = tid & 31;
    const int mg = warp >> 2, ng = warp & 3;     // 2 m-groups x 4 n-groups
    const int g = lane >> 2, tg = lane & 3;
    const int is64 = g_is64;

    // zero both A buffers (covers k-pad 84..103; fills only touch 0..83)
    for (int o = tid * 16; o < SMEM_TOTAL; o += THREADS * 16)
        *reinterpret_cast<uint4*>(smem + o) = make_uint4(0, 0, 0, 0);

    // B fragments in registers (W is constant across tiles): 6 ksteps x 4 nblocks x 2
    uint32_t bfr[6][4][2];
#pragma unroll
    for (int ks = 0; ks < 6; ks++)
#pragma unroll
        for (int nb = 0; nb < 4; nb++) {
            int n = ng * 32 + nb * 8 + g;
#pragma unroll
            for (int p = 0; p < 2; p++) {
                int k = ks * 16 + tg * 2 + p * 8;
                float w0 = (k < KLOG) ? W[k * NOUT + n] : 0.0f;
                float w1 = (k + 1 < KLOG) ? W[(k + 1) * NOUT + n] : 0.0f;
                bfr[ks][nb][p] = pack_h2(w0, w1);
            }
        }
    // bias pairs for this thread's D columns
    float2 bias2[4];
#pragma unroll
    for (int nb = 0; nb < 4; nb++) {
        int col = ng * 32 + nb * 8 + 2 * tg;
        bias2[nb] = *reinterpret_cast<const float2*>(bias + col);
    }

    __syncthreads();   // zero-init visible before first fill/ldmatrix

    const long long nT = (E + 127) >> 7;
    const long long stride = (long long)gridDim.x;
    long long tile = (long long)blockIdx.x;

    float4 f[8];
    float dist = 0.0f;
    if (tile < nT)
        prefetch(bond_feat, bond_index, is64, pos, E, tile, tid, f, dist);

    const int rowoff = (mg * 64 + (lane & 15)) * SA_STRIDE + ((lane >> 4) << 3) * 2;

    int i = 0;
    for (; tile < nT; tile += stride, ++i) {
        const int buf = i & 1;
        char* sA = smem + buf * SA_BUF;
        fill_tile(sA, f, dist, tid);
        if (tile + stride < nT)
            prefetch(bond_feat, bond_index, is64, pos, E, tile + stride, tid, f, dist);

        __syncthreads();

        float acc[4][4][4];
#pragma unroll
        for (int mb = 0; mb < 4; mb++)
#pragma unroll
            for (int nb = 0; nb < 4; nb++)
#pragma unroll
                for (int r = 0; r < 4; r++) acc[mb][nb][r] = 0.0f;

        const uint32_t abase = sb + (uint32_t)buf * SA_BUF + (uint32_t)rowoff;
#pragma unroll
        for (int ks = 0; ks < 6; ks++) {
            uint32_t ah[4][4], al[4][4];
#pragma unroll
            for (int mb = 0; mb < 4; mb++) {
                uint32_t ad = abase + (uint32_t)(mb * 16 * SA_STRIDE + ks * 32);
                LDSM_X4(ah[mb][0], ah[mb][1], ah[mb][2], ah[mb][3], ad);
                LDSM_X4(al[mb][0], al[mb][1], al[mb][2], al[mb][3], ad + SA_SPLIT);
            }
#pragma unroll
            for (int mb = 0; mb < 4; mb++)
#pragma unroll
                for (int nb = 0; nb < 4; nb++) {
                    MMA16816(acc[mb][nb], ah[mb], bfr[ks][nb]);
                    MMA16816(acc[mb][nb], al[mb], bfr[ks][nb]);
                }
        }

        // epilogue: bias + direct float2 stores (32B sectors)
        long long tb = tile << 7;
#pragma unroll
        for (int mb = 0; mb < 4; mb++) {
            long long e0 = tb + mg * 64 + mb * 16 + g;
            long long e1 = e0 + 8;
#pragma unroll
            for (int nb = 0; nb < 4; nb++) {
                int col = ng * 32 + nb * 8 + 2 * tg;
                if (e0 < E) {
                    float2 v = make_float2(acc[mb][nb][0] + bias2[nb].x,
                                           acc[mb][nb][1] + bias2[nb].y);
                    *reinterpret_cast<float2*>(out + e0 * NOUT + col) = v;
                }
                if (e1 < E) {
                    float2 v = make_float2(acc[mb][nb][2] + bias2[nb].x,
                                           acc[mb][nb][3] + bias2[nb].y);
                    *reinterpret_cast<float2*>(out + e1 * NOUT + col) = v;
                }
            }
        }
    }
}

extern "C" void kernel_launch(void* const* d_in, const int* in_sizes, int n_in,
                              void* d_out, int out_size) {
    const float* bond_feat  = (const float*)d_in[0];
    const void*  bond_index = (const void*)d_in[1];
    const float* pos        = (const float*)d_in[2];
    const float* W          = (const float*)d_in[3];
    const float* bias       = (const float*)d_in[4];
    float* out = (float*)d_out;

    long long E = (long long)(in_sizes[0] / 64);
    long long nT = (E + 127) >> 7;
    int grid = (int)(nT < 148 ? nT : 148);

    cudaFuncSetAttribute(bond_embed_mma,
                         cudaFuncAttributeMaxDynamicSharedMemorySize, SMEM_TOTAL);

    detect_idx_kernel<<<1, 256>>>((const unsigned*)bond_index);
    bond_embed_mma<<<grid, THREADS, SMEM_TOTAL>>>(bond_feat, bond_index, pos, W, bias, out, E);
}

// round 4
// speedup vs baseline: 3.3957x; 1.3386x over previous
#include <cuda_runtime.h>
#include <cuda_fp16.h>
#include <cstdint>

#define THREADS 512
#define NOUT 128
#define KLOG 84
#define SA_STRIDE 208              // bytes per A row (104 halves: 96 k + pad)
#define SA_BUF    26624            // 128 rows * 208 B
#define SMEM_TOTAL (2 * SA_BUF)    // double buffered: 53248 B

__device__ int g_is64;

// int64 vs int32 index detection (values < 1e5 => odd words all zero for i64)
__global__ void detect_idx_kernel(const unsigned* __restrict__ bi) {
    int ok = 1;
    for (int i = threadIdx.x; i < 4096; i += blockDim.x)
        if (bi[2 * i + 1] != 0u) ok = 0;
    ok = __syncthreads_and(ok);
    if (threadIdx.x == 0) g_is64 = ok;
}

__device__ __forceinline__ uint32_t smem_u32(const void* p) {
    return (uint32_t)__cvta_generic_to_shared(p);
}

__device__ __forceinline__ uint32_t pack_h2(float a, float b) {
    __half2 h = __floats2half2_rn(a, b);
    return *reinterpret_cast<uint32_t*>(&h);
}

// 8 floats -> 4 packed fp16x2 (rn)
__device__ __forceinline__ uint4 pack8h(const float* x) {
    return make_uint4(pack_h2(x[0], x[1]), pack_h2(x[2], x[3]),
                      pack_h2(x[4], x[5]), pack_h2(x[6], x[7]));
}

#define LDSM_X4(r0, r1, r2, r3, addr)                                          \
    asm volatile("ldmatrix.sync.aligned.m8n8.x4.shared.b16 {%0,%1,%2,%3}, [%4];" \
                 : "=r"(r0), "=r"(r1), "=r"(r2), "=r"(r3) : "r"(addr))

#define MMA16816(c, a, b)                                                      \
    asm volatile("mma.sync.aligned.m16n8k16.row.col.f32.f16.f16.f32 "          \
                 "{%0,%1,%2,%3}, {%4,%5,%6,%7}, {%8,%9}, {%0,%1,%2,%3};"       \
                 : "+f"((c)[0]), "+f"((c)[1]), "+f"((c)[2]), "+f"((c)[3])      \
                 : "r"((a)[0]), "r"((a)[1]), "r"((a)[2]), "r"((a)[3]),         \
                   "r"((b)[0]), "r"((b)[1]))

__device__ __forceinline__ void prefetch(const float* __restrict__ bond_feat,
                                         const void* __restrict__ bidx, int is64,
                                         const float* __restrict__ pos,
                                         long long E, long long tile, int tid,
                                         float4 f[4], float& dist) {
    long long tbase = tile << 7;
    int e = tid >> 2, q = tid & 3;            // 4 threads per edge row
    long long eg = tbase + e;
    if (eg >= E) eg = E - 1;
    const float4* src = reinterpret_cast<const float4*>(bond_feat) + eg * 16 + q * 4;
#pragma unroll
    for (int p = 0; p < 4; p++) f[p] = src[p];
    if (tid < 128) {
        long long eg2 = tbase + tid;
        if (eg2 >= E) eg2 = E - 1;
        long long i0, i1;
        if (is64) {
            const long long* b = (const long long*)bidx;
            i0 = b[eg2]; i1 = b[E + eg2];
        } else {
            const int* b = (const int*)bidx;
            i0 = (long long)b[eg2]; i1 = (long long)b[E + eg2];
        }
        float dx = pos[i0 * 3 + 0] - pos[i1 * 3 + 0];
        float dy = pos[i0 * 3 + 1] - pos[i1 * 3 + 1];
        float dz = pos[i0 * 3 + 2] - pos[i1 * 3 + 2];
        dist = sqrtf(dx * dx + dy * dy + dz * dz);
    }
}

__device__ __forceinline__ void fill_tile(char* sA, const float4 f[4], float dist, int tid) {
    int e = tid >> 2, q = tid & 3;
    int rb = e * SA_STRIDE + q * 32;
    float xs0[8] = { f[0].x, f[0].y, f[0].z, f[0].w, f[1].x, f[1].y, f[1].z, f[1].w };
    float xs1[8] = { f[2].x, f[2].y, f[2].z, f[2].w, f[3].x, f[3].y, f[3].z, f[3].w };
    *reinterpret_cast<uint4*>(sA + rb)      = pack8h(xs0);
    *reinterpret_cast<uint4*>(sA + rb + 16) = pack8h(xs1);
    if (tid < 128) {
        float gg[20];
        const float delta = 10.0f / 19.0f;
        const float coeff = -0.5f / (delta * delta);
#pragma unroll
        for (int j = 0; j < 20; j++) {
            float d = dist - (float)j * delta;
            gg[j] = __expf(coeff * d * d);
        }
        int row = tid * SA_STRIDE;
        *reinterpret_cast<uint4*>(sA + row + 128) = pack8h(gg);
        *reinterpret_cast<uint4*>(sA + row + 144) = pack8h(gg + 8);
        *reinterpret_cast<uint2*>(sA + row + 160) =
            make_uint2(pack_h2(gg[16], gg[17]), pack_h2(gg[18], gg[19]));
    }
}

__global__ void __launch_bounds__(THREADS, 1)
bond_embed_mma(const float* __restrict__ bond_feat,
               const void* __restrict__ bond_index,
               const float* __restrict__ pos,
               const float* __restrict__ W,
               const float* __restrict__ bias,
               float* __restrict__ out,
               long long E) {
    extern __shared__ char smem[];
    const uint32_t sb = smem_u32(smem);
    const int tid = threadIdx.x;
    const int warp = tid >> 5, lane = tid & 31;
    const int mgrp = warp >> 2, ng = warp & 3;   // 4 m-groups x 4 n-groups
    const int g = lane >> 2, tg = lane & 3;
    const int is64 = g_is64;

    // zero both A buffers (covers k-pad 84..95 and row padding; fills touch 0..83 only)
    for (int o = tid * 16; o < SMEM_TOTAL; o += THREADS * 16)
        *reinterpret_cast<uint4*>(smem + o) = make_uint4(0, 0, 0, 0);

    // B fragments in registers (constant across tiles): 6 ksteps x 4 nblocks x 2
    uint32_t bfr[6][4][2];
#pragma unroll
    for (int ks = 0; ks < 6; ks++)
#pragma unroll
        for (int nb = 0; nb < 4; nb++) {
            int n = ng * 32 + nb * 8 + g;
#pragma unroll
            for (int p = 0; p < 2; p++) {
                int k = ks * 16 + tg * 2 + p * 8;
                float w0 = (k < KLOG) ? W[k * NOUT + n] : 0.0f;
                float w1 = (k + 1 < KLOG) ? W[(k + 1) * NOUT + n] : 0.0f;
                bfr[ks][nb][p] = pack_h2(w0, w1);
            }
        }
    float2 bias2[4];
#pragma unroll
    for (int nb = 0; nb < 4; nb++)
        bias2[nb] = *reinterpret_cast<const float2*>(bias + ng * 32 + nb * 8 + 2 * tg);

    __syncthreads();

    const long long nT = (E + 127) >> 7;
    const long long stride = (long long)gridDim.x;
    long long tile = (long long)blockIdx.x;

    float4 f[4];
    float dist = 0.0f;
    if (tile < nT)
        prefetch(bond_feat, bond_index, is64, pos, E, tile, tid, f, dist);

    const int rowoff = (mgrp * 32 + (lane & 15)) * SA_STRIDE + (lane >> 4) * 16;

    int i = 0;
    for (; tile < nT; tile += stride, ++i) {
        const int buf = i & 1;
        fill_tile(smem + buf * SA_BUF, f, dist, tid);
        if (tile + stride < nT)
            prefetch(bond_feat, bond_index, is64, pos, E, tile + stride, tid, f, dist);

        __syncthreads();

        float acc[2][4][4];
#pragma unroll
        for (int mb = 0; mb < 2; mb++)
#pragma unroll
            for (int nb = 0; nb < 4; nb++)
#pragma unroll
                for (int r = 0; r < 4; r++) acc[mb][nb][r] = 0.0f;

        const uint32_t abase = sb + (uint32_t)buf * SA_BUF + (uint32_t)rowoff;
#pragma unroll
        for (int ks = 0; ks < 6; ks++) {
            uint32_t ah[2][4];
#pragma unroll
            for (int mb = 0; mb < 2; mb++) {
                uint32_t ad = abase + (uint32_t)(mb * 16 * SA_STRIDE + ks * 32);
                LDSM_X4(ah[mb][0], ah[mb][1], ah[mb][2], ah[mb][3], ad);
            }
#pragma unroll
            for (int mb = 0; mb < 2; mb++)
#pragma unroll
                for (int nb = 0; nb < 4; nb++)
                    MMA16816(acc[mb][nb], ah[mb], bfr[ks][nb]);
        }

        long long tb = tile << 7;
#pragma unroll
        for (int mb = 0; mb < 2; mb++) {
            long long e0 = tb + mgrp * 32 + mb * 16 + g;
            long long e1 = e0 + 8;
#pragma unroll
            for (int nb = 0; nb < 4; nb++) {
                int col = ng * 32 + nb * 8 + 2 * tg;
                if (e0 < E) {
                    float2 v = make_float2(acc[mb][nb][0] + bias2[nb].x,
                                           acc[mb][nb][1] + bias2[nb].y);
                    *reinterpret_cast<float2*>(out + e0 * NOUT + col) = v;
                }
                if (e1 < E) {
                    float2 v = make_float2(acc[mb][nb][2] + bias2[nb].x,
                                           acc[mb][nb][3] + bias2[nb].y);
                    *reinterpret_cast<float2*>(out + e1 * NOUT + col) = v;
                }
            }
        }
    }
}

extern "C" void kernel_launch(void* const* d_in, const int* in_sizes, int n_in,
                              void* d_out, int out_size) {
    const float* bond_feat  = (const float*)d_in[0];
    const void*  bond_index = (const void*)d_in[1];
    const float* pos        = (const float*)d_in[2];
    const float* W          = (const float*)d_in[3];
    const float* bias       = (const float*)d_in[4];
    float* out = (float*)d_out;

    long long E = (long long)(in_sizes[0] / 64);
    long long nT = (E + 127) >> 7;
    int grid = (int)(nT < 148 ? nT : 148);

    cudaFuncSetAttribute(bond_embed_mma,
                         cudaFuncAttributeMaxDynamicSharedMemorySize, SMEM_TOTAL);

    detect_idx_kernel<<<1, 256>>>((const unsigned*)bond_index);
    bond_embed_mma<<<grid, THREADS, SMEM_TOTAL>>>(bond_feat, bond_index, pos, W, bias, out, E);
}

// round 5
// speedup vs baseline: 3.9179x; 1.1538x over previous
#include <cuda_runtime.h>
#include <cuda_fp16.h>
#include <cstdint>

#define THREADS 256
#define NOUT 128
#define KLOG 84
#define M_TILE 64
#define SA_STRIDE 208              // bytes per A row (104 halves: 96 k + pad)
#define SA_BUF    (M_TILE * SA_STRIDE)   // 13312
#define SMEM_TOTAL (2 * SA_BUF)          // double buffered: 26624 B

__device__ int g_is64;

// int64 vs int32 index detection (values < 1e5 => odd words all zero for i64)
__global__ void detect_idx_kernel(const unsigned* __restrict__ bi) {
    int ok = 1;
    for (int i = threadIdx.x; i < 4096; i += blockDim.x)
        if (bi[2 * i + 1] != 0u) ok = 0;
    ok = __syncthreads_and(ok);
    if (threadIdx.x == 0) g_is64 = ok;
}

__device__ __forceinline__ uint32_t smem_u32(const void* p) {
    return (uint32_t)__cvta_generic_to_shared(p);
}

__device__ __forceinline__ uint32_t pack_h2(float a, float b) {
    __half2 h = __floats2half2_rn(a, b);
    return *reinterpret_cast<uint32_t*>(&h);
}

__device__ __forceinline__ uint4 pack8h(const float* x) {
    return make_uint4(pack_h2(x[0], x[1]), pack_h2(x[2], x[3]),
                      pack_h2(x[4], x[5]), pack_h2(x[6], x[7]));
}

#define LDSM_X4(r0, r1, r2, r3, addr)                                          \
    asm volatile("ldmatrix.sync.aligned.m8n8.x4.shared.b16 {%0,%1,%2,%3}, [%4];" \
                 : "=r"(r0), "=r"(r1), "=r"(r2), "=r"(r3) : "r"(addr))

#define MMA16816(c, a, b)                                                      \
    asm volatile("mma.sync.aligned.m16n8k16.row.col.f32.f16.f16.f32 "          \
                 "{%0,%1,%2,%3}, {%4,%5,%6,%7}, {%8,%9}, {%0,%1,%2,%3};"       \
                 : "+f"((c)[0]), "+f"((c)[1]), "+f"((c)[2]), "+f"((c)[3])      \
                 : "r"((a)[0]), "r"((a)[1]), "r"((a)[2]), "r"((a)[3]),         \
                   "r"((b)[0]), "r"((b)[1]))

__device__ __forceinline__ void prefetch(const float* __restrict__ bond_feat,
                                         const void* __restrict__ bidx, int is64,
                                         const float* __restrict__ pos,
                                         long long E, long long tile, int tid,
                                         float4 f[4], float& dist) {
    long long tbase = tile << 6;
    int e = tid >> 2, q = tid & 3;            // 4 threads per edge row
    long long eg = tbase + e;
    if (eg >= E) eg = E - 1;
    const float4* src = reinterpret_cast<const float4*>(bond_feat) + eg * 16 + q * 4;
#pragma unroll
    for (int p = 0; p < 4; p++) f[p] = src[p];
    if (tid < M_TILE) {
        long long eg2 = tbase + tid;
        if (eg2 >= E) eg2 = E - 1;
        long long i0, i1;
        if (is64) {
            const long long* b = (const long long*)bidx;
            i0 = b[eg2]; i1 = b[E + eg2];
        } else {
            const int* b = (const int*)bidx;
            i0 = (long long)b[eg2]; i1 = (long long)b[E + eg2];
        }
        float dx = pos[i0 * 3 + 0] - pos[i1 * 3 + 0];
        float dy = pos[i0 * 3 + 1] - pos[i1 * 3 + 1];
        float dz = pos[i0 * 3 + 2] - pos[i1 * 3 + 2];
        dist = sqrtf(dx * dx + dy * dy + dz * dz);
    }
}

__device__ __forceinline__ void fill_tile(char* sA, const float4 f[4], float dist, int tid) {
    int e = tid >> 2, q = tid & 3;
    int rb = e * SA_STRIDE + q * 32;
    float xs0[8] = { f[0].x, f[0].y, f[0].z, f[0].w, f[1].x, f[1].y, f[1].z, f[1].w };
    float xs1[8] = { f[2].x, f[2].y, f[2].z, f[2].w, f[3].x, f[3].y, f[3].z, f[3].w };
    *reinterpret_cast<uint4*>(sA + rb)      = pack8h(xs0);
    *reinterpret_cast<uint4*>(sA + rb + 16) = pack8h(xs1);
    if (tid < M_TILE) {
        float gg[20];
        const float delta = 10.0f / 19.0f;
        const float coeff = -0.5f / (delta * delta);
#pragma unroll
        for (int j = 0; j < 20; j++) {
            float d = dist - (float)j * delta;
            gg[j] = __expf(coeff * d * d);
        }
        int row = tid * SA_STRIDE;
        *reinterpret_cast<uint4*>(sA + row + 128) = pack8h(gg);
        *reinterpret_cast<uint4*>(sA + row + 144) = pack8h(gg + 8);
        *reinterpret_cast<uint2*>(sA + row + 160) =
            make_uint2(pack_h2(gg[16], gg[17]), pack_h2(gg[18], gg[19]));
    }
}

__global__ void __launch_bounds__(THREADS, 2)
bond_embed_mma(const float* __restrict__ bond_feat,
               const void* __restrict__ bond_index,
               const float* __restrict__ pos,
               const float* __restrict__ W,
               const float* __restrict__ bias,
               float* __restrict__ out,
               long long E) {
    extern __shared__ char smem[];
    const uint32_t sb = smem_u32(smem);
    const int tid = threadIdx.x;
    const int warp = tid >> 5, lane = tid & 31;
    const int mgrp = warp >> 2, ng = warp & 3;   // 2 m-groups x 4 n-groups
    const int g = lane >> 2, tg = lane & 3;
    const int is64 = g_is64;

    // zero both A buffers (covers k-pad 84..103; fills touch k 0..83 only)
    for (int o = tid * 16; o < SMEM_TOTAL; o += THREADS * 16)
        *reinterpret_cast<uint4*>(smem + o) = make_uint4(0, 0, 0, 0);

    // B fragments in registers (constant across tiles): 6 ksteps x 4 nblocks x 2
    uint32_t bfr[6][4][2];
#pragma unroll
    for (int ks = 0; ks < 6; ks++)
#pragma unroll
        for (int nb = 0; nb < 4; nb++) {
            int n = ng * 32 + nb * 8 + g;
#pragma unroll
            for (int p = 0; p < 2; p++) {
                int k = ks * 16 + tg * 2 + p * 8;
                float w0 = (k < KLOG) ? W[k * NOUT + n] : 0.0f;
                float w1 = (k + 1 < KLOG) ? W[(k + 1) * NOUT + n] : 0.0f;
                bfr[ks][nb][p] = pack_h2(w0, w1);
            }
        }
    float2 bias2[4];
#pragma unroll
    for (int nb = 0; nb < 4; nb++)
        bias2[nb] = *reinterpret_cast<const float2*>(bias + ng * 32 + nb * 8 + 2 * tg);

    __syncthreads();

    const long long nT = (E + M_TILE - 1) >> 6;
    const long long stride = (long long)gridDim.x;
    long long tile = (long long)blockIdx.x;

    float4 f[4];
    float dist = 0.0f;
    if (tile < nT)
        prefetch(bond_feat, bond_index, is64, pos, E, tile, tid, f, dist);

    const int rowoff = (mgrp * 32 + (lane & 15)) * SA_STRIDE + (lane >> 4) * 16;

    int i = 0;
    for (; tile < nT; tile += stride, ++i) {
        const int buf = i & 1;
        fill_tile(smem + buf * SA_BUF, f, dist, tid);
        if (tile + stride < nT)
            prefetch(bond_feat, bond_index, is64, pos, E, tile + stride, tid, f, dist);

        __syncthreads();

        float acc[2][4][4];
#pragma unroll
        for (int mb = 0; mb < 2; mb++)
#pragma unroll
            for (int nb = 0; nb < 4; nb++)
#pragma unroll
                for (int r = 0; r < 4; r++) acc[mb][nb][r] = 0.0f;

        const uint32_t abase = sb + (uint32_t)buf * SA_BUF + (uint32_t)rowoff;
#pragma unroll
        for (int ks = 0; ks < 6; ks++) {
            uint32_t ah[2][4];
#pragma unroll
            for (int mb = 0; mb < 2; mb++) {
                uint32_t ad = abase + (uint32_t)(mb * 16 * SA_STRIDE + ks * 32);
                LDSM_X4(ah[mb][0], ah[mb][1], ah[mb][2], ah[mb][3], ad);
            }
#pragma unroll
            for (int mb = 0; mb < 2; mb++)
#pragma unroll
                for (int nb = 0; nb < 4; nb++)
                    MMA16816(acc[mb][nb], ah[mb], bfr[ks][nb]);
        }

        long long tb = tile << 6;
#pragma unroll
        for (int mb = 0; mb < 2; mb++) {
            long long e0 = tb + mgrp * 32 + mb * 16 + g;
            long long e1 = e0 + 8;
#pragma unroll
            for (int nb = 0; nb < 4; nb++) {
                int col = ng * 32 + nb * 8 + 2 * tg;
                if (e0 < E) {
                    float2 v = make_float2(acc[mb][nb][0] + bias2[nb].x,
                                           acc[mb][nb][1] + bias2[nb].y);
                    *reinterpret_cast<float2*>(out + e0 * NOUT + col) = v;
                }
                if (e1 < E) {
                    float2 v = make_float2(acc[mb][nb][2] + bias2[nb].x,
                                           acc[mb][nb][3] + bias2[nb].y);
                    *reinterpret_cast<float2*>(out + e1 * NOUT + col) = v;
                }
            }
        }
    }
}

extern "C" void kernel_launch(void* const* d_in, const int* in_sizes, int n_in,
                              void* d_out, int out_size) {
    const float* bond_feat  = (const float*)d_in[0];
    const void*  bond_index = (const void*)d_in[1];
    const float* pos        = (const float*)d_in[2];
    const float* W          = (const float*)d_in[3];
    const float* bias       = (const float*)d_in[4];
    float* out = (float*)d_out;

    long long E = (long long)(in_sizes[0] / 64);
    long long nT = (E + M_TILE - 1) >> 6;
    int grid = (int)(nT < 296 ? nT : 296);

    cudaFuncSetAttribute(bond_embed_mma,
                         cudaFuncAttributeMaxDynamicSharedMemorySize, SMEM_TOTAL);

    detect_idx_kernel<<<1, 256>>>((const unsigned*)bond_index);
    bond_embed_mma<<<grid, THREADS, SMEM_TOTAL>>>(bond_feat, bond_index, pos, W, bias, out, E);
}